// round 11
// baseline (speedup 1.0000x reference)
#include <cuda_runtime.h>
#include <cuda_fp16.h>

typedef unsigned int u32;

// Problem constants: grid (1, C, S, S, S), N points.
#define GS 160
#define GC 12
#define VOXB 24                       // bytes per voxel (12 x fp16, unpadded)
#define ROWB (GS * VOXB)              // h-stride in bytes: 3840
#define SLABB (GS * GS * VOXB)        // d-stride in bytes: 614400
#define CH_STRIDE (GS * GS * GS)      // channel stride in source layout (floats)

// Scratch: fp16 channel-interleaved UNPADDED grid [D][H][W][12] = 98.3MB
// (< 126MB L2 -> stays cache-resident across graph replays). +256B pad for
// the 64B-window over-read at the end.
__device__ __half g_ilv[(long long)GS * GS * GS * GC + 128];

// ---------------------------------------------------------------------------
// Kernel 1: transpose+convert [C,D,H,W] f32 -> [D,H,W,12] f16 (24B voxels).
// One block per (d,h) row. Streaming reads (.cs) so the source doesn't evict
// the interleaved grid from L2; write one contiguous 3840B run.
// ---------------------------------------------------------------------------
__global__ void __launch_bounds__(256) transpose_ilv_kernel(const float* __restrict__ grid) {
    __shared__ float tile[GC][GS + 1];        // padded: conflict-free column reads
    __shared__ u32 rowu[GS * GC / 2];         // 960 uints = the packed 3840B row

    const int row = blockIdx.x;               // row = d*GS + h
    const float* src = grid + (long long)row * GS;

    for (int idx = threadIdx.x; idx < GC * (GS / 4); idx += blockDim.x) {
        int c = idx / (GS / 4);
        int v = idx - c * (GS / 4);
        float4 x = __ldcs(reinterpret_cast<const float4*>(src + (long long)c * CH_STRIDE + v * 4));
        tile[c][4 * v + 0] = x.x;
        tile[c][4 * v + 1] = x.y;
        tile[c][4 * v + 2] = x.z;
        tile[c][4 * v + 3] = x.w;
    }
    __syncthreads();

    // pack: voxel w occupies uints [w*6, w*6+6); uint i holds ch(2i), ch(2i+1)
    for (int t = threadIdx.x; t < GS * 6; t += blockDim.x) {
        int w = t / 6;
        int i = t - 6 * w;
        __half2 h = __floats2half2_rn(tile[2 * i][w], tile[2 * i + 1][w]);
        rowu[t] = *reinterpret_cast<const u32*>(&h);
    }
    __syncthreads();

    uint4* dst = reinterpret_cast<uint4*>(reinterpret_cast<char*>(g_ilv) + (long long)row * ROWB);
    const uint4* srcu = reinterpret_cast<const uint4*>(rowu);
    for (int j = threadIdx.x; j < ROWB / 16; j += blockDim.x)   // 240 uint4
        dst[j] = srcu[j];
}

// ---------------------------------------------------------------------------
// Kernel 2: WARP-COOPERATIVE trilinear gather, 24B voxels.
// 4 lanes per point, 8 points per warp. Each point's (d,h) row-pair is 48B
// inside a 64B aligned window; lane j loads window chunk j (16B). Per-element
// static masks map window halves to {w0, w1, garbage}. Channel re-gather via
// padded smem staging; coalesced float4 stores with streaming hint.
// ---------------------------------------------------------------------------
__global__ void __launch_bounds__(256) trilerp_kernel(
    const float* __restrict__ xyz,
    const float* __restrict__ xyz_min,
    const float* __restrict__ xyz_max,
    float* __restrict__ out,
    int N)
{
    __shared__ float buf[8][8][33];           // [warp][point][window-half], padded

    const int warp_g = (blockIdx.x * blockDim.x + threadIdx.x) >> 5;
    const int wb  = (threadIdx.x >> 5) & 7;   // warp-in-block
    const int lane = threadIdx.x & 31;
    const int sub = lane >> 2;                // point-in-group 0..7
    const int j   = lane & 3;                 // 16B chunk 0..3

    int n = warp_g * 8 + sub;
    const bool valid = (n < N);
    n = min(n, N - 1);                        // clamp: loads in-bounds, stores predicated

    const float px = __ldcs(&xyz[3 * n + 0]);
    const float py = __ldcs(&xyz[3 * n + 1]);
    const float pz = __ldcs(&xyz[3 * n + 2]);

    const float mn0 = __ldg(&xyz_min[0]);
    const float mn1 = __ldg(&xyz_min[1]);
    const float mn2 = __ldg(&xyz_min[2]);
    const float mx0 = __ldg(&xyz_max[0]);
    const float mx1 = __ldg(&xyz_max[1]);
    const float mx2 = __ldg(&xyz_max[2]);

    const float hi  = (float)(GS - 1);        // 159
    const float hi2 = (float)(GS - 2);        // 158

    float ud = (px - mn0) * (hi / (mx0 - mn0));
    ud = fminf(fmaxf(ud, 0.0f), hi);
    float d0f = fminf(floorf(ud), hi2);
    float fd = ud - d0f;
    int d0 = (int)d0f;

    float uh = (py - mn1) * (hi / (mx1 - mn1));
    uh = fminf(fmaxf(uh, 0.0f), hi);
    float h0f = fminf(floorf(uh), hi2);
    float fh = uh - h0f;
    int h0 = (int)h0f;

    float uw = (pz - mn2) * (hi / (mx2 - mn2));
    uw = fminf(fmaxf(uw, 0.0f), hi);
    float w0f = fminf(floorf(uw), hi2);
    float fw = uw - w0f;
    int w0 = (int)w0f;

    const u32 vox = (u32)(d0 * GS + h0) * (u32)GS + (u32)w0;
    const int sel = (int)(vox & 1u);          // w0 parity == vox parity (strides even)
    const u32 b0 = vox * 24u - (u32)(sel * 8) + (u32)j * 16u;   // 16B-aligned

    // Static per-element class: window half e = 8j+i; pair half t = e - 4*sel.
    // t in [0,12): w0 channel t; t in [12,24): w1 channel t-12; else garbage.
    float selA[8], selB[8];
#pragma unroll
    for (int i = 0; i < 8; i++) {
        int t = 8 * j + i - 4 * sel;
        selA[i] = (t >= 0 && t < 12) ? 1.0f : 0.0f;
        selB[i] = (t >= 12 && t < 24) ? 1.0f : 0.0f;
    }

    const float omfd = 1.0f - fd, omfh = 1.0f - fh, omfw = 1.0f - fw;
    const float coef[4] = { omfd * omfh, omfd * fh, fd * omfh, fd * fh };
    const u32 qoff[4] = { 0u, (u32)ROWB, (u32)SLABB, (u32)(SLABB + ROWB) };

    // Batch the 4 cooperative LDG.128 for MLP.
    uint4 r[4];
#pragma unroll
    for (int q = 0; q < 4; q++)
        r[q] = *reinterpret_cast<const uint4*>(
            reinterpret_cast<const char*>(g_ilv) + (b0 + qoff[q]));

    float acc[8];
#pragma unroll
    for (int k = 0; k < 8; k++) acc[k] = 0.0f;

#pragma unroll
    for (int q = 0; q < 4; q++) {
        const float wA = coef[q] * omfw;
        const float wB = coef[q] * fw;
        const __half2* hp = reinterpret_cast<const __half2*>(&r[q]);
#pragma unroll
        for (int i = 0; i < 4; i++) {
            float2 f = __half22float2(hp[i]);
            acc[2 * i + 0] += (selA[2 * i + 0] * wA + selB[2 * i + 0] * wB) * f.x;
            acc[2 * i + 1] += (selA[2 * i + 1] * wA + selB[2 * i + 1] * wB) * f.y;
        }
    }

    // Stage to padded smem: slot = window half index (conflict-free banks).
#pragma unroll
    for (int i = 0; i < 8; i++)
        buf[wb][sub][8 * j + i] = acc[i];
    __syncwarp();

    // Re-gather: lane (sub, j<3) emits channels 4j..4j+3 of its point.
    if (valid && j < 3) {
        float4 v;
        const float* bp = buf[wb][sub];
        const int e0 = 4 * j + 4 * sel;       // window half of channel 4j (w0 side)
        v.x = bp[e0 + 0] + bp[e0 + 12];
        v.y = bp[e0 + 1] + bp[e0 + 13];
        v.z = bp[e0 + 2] + bp[e0 + 14];
        v.w = bp[e0 + 3] + bp[e0 + 15];
        __stcs(reinterpret_cast<float4*>(out + (long long)n * GC + 4 * j), v);
    }
}

// ---------------------------------------------------------------------------
// kernel_launch
// Inputs (metadata order): xyz [N,3] f32, grid [1,12,160,160,160] f32,
//                          xyz_min [3] f32, xyz_max [3] f32
// Output: [N, 12] f32
// ---------------------------------------------------------------------------
extern "C" void kernel_launch(void* const* d_in, const int* in_sizes, int n_in,
                              void* d_out, int out_size) {
    const float* xyz     = (const float*)d_in[0];
    const float* grid    = (const float*)d_in[1];
    const float* xyz_min = (const float*)d_in[2];
    const float* xyz_max = (const float*)d_in[3];
    float* out = (float*)d_out;

    const int N = in_sizes[0] / 3;

    transpose_ilv_kernel<<<GS * GS, 256>>>(grid);

    // 8 points per warp, 8 warps per block -> 64 points per block
    const int blocks = (N + 63) / 64;
    trilerp_kernel<<<blocks, 256>>>(xyz, xyz_min, xyz_max, out, N);
}

// round 12
// speedup vs baseline: 1.3403x; 1.3403x over previous
#include <cuda_runtime.h>
#include <cuda_fp16.h>

typedef unsigned int u32;

// Problem constants: grid (1, C, S, S, S), N points.
#define GS 160
#define GC 12
#define CH_STRIDE (GS * GS * GS)      // channel stride in source layout (floats)
#define S3 (GS * GS * GS)             // 4,096,000 voxels

// Split channel-interleaved fp16 grid:
//   gA: [D][H][W][8]  = ch0-7,  16B/voxel, 64MB
//   gB: [D][H][W][4]  = ch8-11,  8B/voxel, 32MB
// Total 96MB < 126MB L2. All accesses naturally aligned; no over-read
// (max voxel index touched is exactly S3-1).
__device__ __half gA[(long long)S3 * 8];
__device__ __half gB[(long long)S3 * 4];

// ---------------------------------------------------------------------------
// Kernel 1: transpose+convert [C,D,H,W] f32 -> split gA/gB fp16.
// One block per (d,h) row: read 12x40 float4 (coalesced), write one 2560B
// run to gA and one 1280B run to gB (both coalesced).
// ---------------------------------------------------------------------------
__global__ void __launch_bounds__(256) transpose_ilv_kernel(const float* __restrict__ grid) {
    __shared__ float tile[GC][GS];
    const int row = blockIdx.x;          // row = d*GS + h
    const float* src = grid + (long long)row * GS;

    for (int idx = threadIdx.x; idx < GC * (GS / 4); idx += blockDim.x) {
        int c = idx / (GS / 4);
        int v = idx - c * (GS / 4);
        float4 x = *reinterpret_cast<const float4*>(src + (long long)c * CH_STRIDE + v * 4);
        tile[c][4 * v + 0] = x.x;
        tile[c][4 * v + 1] = x.y;
        tile[c][4 * v + 2] = x.z;
        tile[c][4 * v + 3] = x.w;
    }
    __syncthreads();

    if (threadIdx.x < GS) {
        const int w = threadIdx.x;
        const long long vox = (long long)row * GS + w;

        __half2 a[4];
#pragma unroll
        for (int i = 0; i < 4; i++)
            a[i] = __floats2half2_rn(tile[2 * i][w], tile[2 * i + 1][w]);
        *reinterpret_cast<uint4*>(gA + vox * 8) = *reinterpret_cast<const uint4*>(a);

        __half2 b[2];
#pragma unroll
        for (int i = 0; i < 2; i++)
            b[i] = __floats2half2_rn(tile[8 + 2 * i][w], tile[9 + 2 * i][w]);
        *reinterpret_cast<uint2*>(gB + vox * 4) = *reinterpret_cast<const uint2*>(b);
    }
}

// ---------------------------------------------------------------------------
// Kernel 2: WARP-COOPERATIVE trilinear gather over the split layout.
// 4 lanes per point, 8 points per warp.
//   lane j=0: gA voxel w0 (16B)   j=1: gA voxel w1 (16B)
//   lane j=2: gB voxel w0 ( 8B)   j=3: gB voxel w1 ( 8B)
// Each lane's elements all share one weight per pair: coef[q]*(j&1?fw:omfw).
// shfl_xor(1) combines w0+w1; lanes j=0,1,2 store one float4 each.
// ---------------------------------------------------------------------------
__global__ void __launch_bounds__(256) trilerp_kernel(
    const float* __restrict__ xyz,
    const float* __restrict__ xyz_min,
    const float* __restrict__ xyz_max,
    float* __restrict__ out,
    int N)
{
    const int warp_g = (blockIdx.x * blockDim.x + threadIdx.x) >> 5;
    const int lane = threadIdx.x & 31;
    const int sub = lane >> 2;            // point-in-group 0..7
    const int j   = lane & 3;             // role 0..3

    int n = warp_g * 8 + sub;
    const bool valid = (n < N);
    n = min(n, N - 1);                    // clamp: loads in-bounds, stores predicated

    const float px = xyz[3 * n + 0];
    const float py = xyz[3 * n + 1];
    const float pz = xyz[3 * n + 2];

    const float mn0 = __ldg(&xyz_min[0]);
    const float mn1 = __ldg(&xyz_min[1]);
    const float mn2 = __ldg(&xyz_min[2]);
    const float mx0 = __ldg(&xyz_max[0]);
    const float mx1 = __ldg(&xyz_max[1]);
    const float mx2 = __ldg(&xyz_max[2]);

    const float hi  = (float)(GS - 1);    // 159
    const float hi2 = (float)(GS - 2);    // 158

    float ud = (px - mn0) * (hi / (mx0 - mn0));
    ud = fminf(fmaxf(ud, 0.0f), hi);
    float d0f = fminf(floorf(ud), hi2);
    float fd = ud - d0f;
    int d0 = (int)d0f;

    float uh = (py - mn1) * (hi / (mx1 - mn1));
    uh = fminf(fmaxf(uh, 0.0f), hi);
    float h0f = fminf(floorf(uh), hi2);
    float fh = uh - h0f;
    int h0 = (int)h0f;

    float uw = (pz - mn2) * (hi / (mx2 - mn2));
    uw = fminf(fmaxf(uw, 0.0f), hi);
    float w0f = fminf(floorf(uw), hi2);
    float fw = uw - w0f;
    int w0 = (int)w0f;

    const u32 v0 = (u32)(d0 * GS + h0) * (u32)GS + (u32)w0;
    const u32 vq[4] = { v0, v0 + GS, v0 + GS * GS, v0 + GS * GS + GS };

    const float omfd = 1.0f - fd, omfh = 1.0f - fh, omfw = 1.0f - fw;
    const float coef[4] = { omfd * omfh, omfd * fh, fd * omfh, fd * fh };
    const float wsel = (j & 1) ? fw : omfw;   // this lane's w0/w1 side

    // Batch the 4 loads for MLP. j<2 -> 16B from gA; j>=2 -> 8B from gB.
    uint4 r[4];
    if (j < 2) {
#pragma unroll
        for (int q = 0; q < 4; q++)
            r[q] = *reinterpret_cast<const uint4*>(gA + (long long)(vq[q] + (u32)j) * 8);
    } else {
#pragma unroll
        for (int q = 0; q < 4; q++) {
            uint2 t = *reinterpret_cast<const uint2*>(gB + (long long)(vq[q] + (u32)(j - 2)) * 4);
            r[q].x = t.x; r[q].y = t.y; r[q].z = 0u; r[q].w = 0u;
        }
    }

    float acc[8];
#pragma unroll
    for (int k = 0; k < 8; k++) acc[k] = 0.0f;

#pragma unroll
    for (int q = 0; q < 4; q++) {
        const float w = coef[q] * wsel;
        const __half2* hp = reinterpret_cast<const __half2*>(&r[q]);
#pragma unroll
        for (int i = 0; i < 4; i++) {
            float2 f = __half22float2(hp[i]);
            acc[2 * i + 0] += w * f.x;
            acc[2 * i + 1] += w * f.y;
        }
    }

    // Combine w0 (even j) with w1 (odd j) within each role pair.
#pragma unroll
    for (int k = 0; k < 8; k++)
        acc[k] += __shfl_xor_sync(0xffffffffu, acc[k], 1);

    // Store: lane j=0 -> ch0-3, j=1 -> ch4-7 (same data as j=0, upper half),
    // j=2 -> ch8-11. 24 active lanes per warp, contiguous 384B per warp.
    if (valid) {
        float* o = out + (long long)n * GC;
        if (j == 0)
            *reinterpret_cast<float4*>(o)     = make_float4(acc[0], acc[1], acc[2], acc[3]);
        else if (j == 1)
            *reinterpret_cast<float4*>(o + 4) = make_float4(acc[4], acc[5], acc[6], acc[7]);
        else if (j == 2)
            *reinterpret_cast<float4*>(o + 8) = make_float4(acc[0], acc[1], acc[2], acc[3]);
    }
}

// ---------------------------------------------------------------------------
// kernel_launch
// Inputs (metadata order): xyz [N,3] f32, grid [1,12,160,160,160] f32,
//                          xyz_min [3] f32, xyz_max [3] f32
// Output: [N, 12] f32
// ---------------------------------------------------------------------------
extern "C" void kernel_launch(void* const* d_in, const int* in_sizes, int n_in,
                              void* d_out, int out_size) {
    const float* xyz     = (const float*)d_in[0];
    const float* grid    = (const float*)d_in[1];
    const float* xyz_min = (const float*)d_in[2];
    const float* xyz_max = (const float*)d_in[3];
    float* out = (float*)d_out;

    const int N = in_sizes[0] / 3;

    transpose_ilv_kernel<<<GS * GS, 256>>>(grid);

    // 8 points per warp, 8 warps per block -> 64 points per block
    const int blocks = (N + 63) / 64;
    trilerp_kernel<<<blocks, 256>>>(xyz, xyz_min, xyz_max, out, N);
}

// round 15
// speedup vs baseline: 1.4401x; 1.0745x over previous
#include <cuda_runtime.h>
#include <cuda_fp16.h>

typedef unsigned int u32;

// Problem constants: grid (1, C, S, S, S), N points.
#define GS 160
#define GC 12
#define VOXH 16                       // padded halves per voxel (32 bytes)
#define VOXB 32                       // bytes per voxel
#define CH_STRIDE (GS * GS * GS)      // channel stride in source layout (floats)
#define ROWB (GS * VOXB)              // h-stride in bytes: 5120
#define SLABB (GS * GS * VOXB)        // d-stride in bytes: 819200
#define RPB 4                         // transpose rows per block

// Scratch: fp16 channel-interleaved padded grid [D][H][W][16]. 131 MB.
__device__ __half g_ilv[(long long)GS * GS * GS * VOXH];

// ---------------------------------------------------------------------------
// Kernel 1 (v2): transpose+convert [C,D,H,W] f32 -> [D,H,W,16] f16.
// 4 (d,h) rows per block (rows are memory-contiguous: 640 consecutive floats
// = 160 consecutive float4 per channel). Read fully coalesced into float4
// smem tiles; write phase uses ALL 256 threads across 640 voxels (32B each,
// consecutive -> perfectly coalesced 20KB run per block).
// ---------------------------------------------------------------------------
__global__ void __launch_bounds__(256) transpose_ilv_kernel(const float* __restrict__ grid) {
    __shared__ float4 tile4[GC][RPB * 40];    // 12 x 160 float4 = 30720B

    const int row0 = blockIdx.x * RPB;        // first of 4 consecutive rows

    // Read: 12 channels x 160 float4 (contiguous per channel).
    for (int idx = threadIdx.x; idx < GC * RPB * 40; idx += 256) {
        const int c = idx / (RPB * 40);
        const int rem = idx - c * (RPB * 40); // r*40 + v
        tile4[c][rem] = *reinterpret_cast<const float4*>(
            grid + (long long)c * CH_STRIDE + (long long)row0 * GS + rem * 4);
    }
    __syncthreads();

    // Write: 640 voxels; thread handles voxel f = r*160+w.
    const float* tile = reinterpret_cast<const float*>(tile4);   // [c][RPB*160]
    for (int f = threadIdx.x; f < RPB * GS; f += 256) {
        __half2 v[8];
#pragma unroll
        for (int i = 0; i < 6; i++)
            v[i] = __floats2half2_rn(tile[(2 * i) * (RPB * GS) + f],
                                     tile[(2 * i + 1) * (RPB * GS) + f]);
        v[6] = __floats2half2_rn(0.f, 0.f);
        v[7] = v[6];
        uint4* dst = reinterpret_cast<uint4*>(g_ilv + ((long long)row0 * GS + f) * VOXH);
        dst[0] = *reinterpret_cast<const uint4*>(&v[0]);
        dst[1] = *reinterpret_cast<const uint4*>(&v[4]);
    }
}

// ---------------------------------------------------------------------------
// Kernel 2: WARP-COOPERATIVE trilinear gather (R9-proven, 89.9us).
// 4 lanes per point, 8 points per warp. Each LDG.128 loads one 64B (d,h)
// row-pair for all 8 points cooperatively (lanes 4p..4p+3 = 4 x 16B chunks).
//   chunk j=0: w0 voxel ch0-7   | j=1: w0 voxel ch8-11+pad
//   chunk j=2: w1 voxel ch0-7   | j=3: w1 voxel ch8-11+pad
// After accumulating the 4 pairs, shfl.xor(2) combines w0+w1 halves.
// ---------------------------------------------------------------------------
__global__ void __launch_bounds__(256) trilerp_kernel(
    const float* __restrict__ xyz,
    const float* __restrict__ xyz_min,
    const float* __restrict__ xyz_max,
    float* __restrict__ out,
    int N)
{
    const int warp_g = (blockIdx.x * blockDim.x + threadIdx.x) >> 5;
    const int lane = threadIdx.x & 31;
    const int sub = lane >> 2;            // point-in-group 0..7
    const int j   = lane & 3;             // 16B chunk 0..3

    int n = warp_g * 8 + sub;
    const bool valid = (n < N);
    n = min(n, N - 1);                    // clamp: loads stay in-bounds, stores predicated

    const float px = xyz[3 * n + 0];
    const float py = xyz[3 * n + 1];
    const float pz = xyz[3 * n + 2];

    const float mn0 = __ldg(&xyz_min[0]);
    const float mn1 = __ldg(&xyz_min[1]);
    const float mn2 = __ldg(&xyz_min[2]);
    const float mx0 = __ldg(&xyz_max[0]);
    const float mx1 = __ldg(&xyz_max[1]);
    const float mx2 = __ldg(&xyz_max[2]);

    const float hi  = (float)(GS - 1);    // 159
    const float hi2 = (float)(GS - 2);    // 158

    float ud = (px - mn0) * (hi / (mx0 - mn0));
    ud = fminf(fmaxf(ud, 0.0f), hi);
    float d0f = fminf(floorf(ud), hi2);
    float fd = ud - d0f;
    int d0 = (int)d0f;

    float uh = (py - mn1) * (hi / (mx1 - mn1));
    uh = fminf(fmaxf(uh, 0.0f), hi);
    float h0f = fminf(floorf(uh), hi2);
    float fh = uh - h0f;
    int h0 = (int)h0f;

    float uw = (pz - mn2) * (hi / (mx2 - mn2));
    uw = fminf(fmaxf(uw, 0.0f), hi);
    float w0f = fminf(floorf(uw), hi2);
    float fw = uw - w0f;
    int w0 = (int)w0f;

    const u32 b0 = ((u32)(d0 * GS + h0) * GS + (u32)w0) * (u32)VOXB + (u32)j * 16u;

    const float omfd = 1.0f - fd, omfh = 1.0f - fh, omfw = 1.0f - fw;
    const float coef[4] = { omfd * omfh, omfd * fh, fd * omfh, fd * fh };
    const float wsel = (j < 2) ? omfw : fw;   // this lane's w0/w1 side
    const u32 qoff[4] = { 0u, (u32)ROWB, (u32)SLABB, (u32)(SLABB + ROWB) };

    // Batch the 4 cooperative LDG.128 for MLP.
    uint4 r[4];
#pragma unroll
    for (int q = 0; q < 4; q++)
        r[q] = *reinterpret_cast<const uint4*>(
            reinterpret_cast<const char*>(g_ilv) + (b0 + qoff[q]));

    float acc[8];
#pragma unroll
    for (int k = 0; k < 8; k++) acc[k] = 0.0f;

#pragma unroll
    for (int q = 0; q < 4; q++) {
        const float w = coef[q] * wsel;
        const __half2* hp = reinterpret_cast<const __half2*>(&r[q]);
#pragma unroll
        for (int i = 0; i < 4; i++) {
            float2 f = __half22float2(hp[i]);
            acc[2 * i + 0] += w * f.x;
            acc[2 * i + 1] += w * f.y;
        }
    }

    // Combine w0 (lanes j=0,1) with w1 (lanes j=2,3): xor lane by 2.
#pragma unroll
    for (int k = 0; k < 8; k++)
        acc[k] += __shfl_xor_sync(0xffffffffu, acc[k], 2);

    if (valid) {
        float* o = out + (long long)n * GC;
        if (j == 0) {
            *reinterpret_cast<float4*>(o)     = make_float4(acc[0], acc[1], acc[2], acc[3]);
            *reinterpret_cast<float4*>(o + 4) = make_float4(acc[4], acc[5], acc[6], acc[7]);
        } else if (j == 1) {
            *reinterpret_cast<float4*>(o + 8) = make_float4(acc[0], acc[1], acc[2], acc[3]);
        }
    }
}

// ---------------------------------------------------------------------------
// kernel_launch
// Inputs (metadata order): xyz [N,3] f32, grid [1,12,160,160,160] f32,
//                          xyz_min [3] f32, xyz_max [3] f32
// Output: [N, 12] f32
// ---------------------------------------------------------------------------
extern "C" void kernel_launch(void* const* d_in, const int* in_sizes, int n_in,
                              void* d_out, int out_size) {
    const float* xyz     = (const float*)d_in[0];
    const float* grid    = (const float*)d_in[1];
    const float* xyz_min = (const float*)d_in[2];
    const float* xyz_max = (const float*)d_in[3];
    float* out = (float*)d_out;

    const int N = in_sizes[0] / 3;

    transpose_ilv_kernel<<<(GS * GS) / RPB, 256>>>(grid);

    // 8 points per warp, 8 warps per block -> 64 points per block
    const int blocks = (N + 63) / 64;
    trilerp_kernel<<<blocks, 256>>>(xyz, xyz_min, xyz_max, out, N);
}